// round 8
// baseline (speedup 1.0000x reference)
#include <cuda_runtime.h>
#include <cuda_bf16.h>
#include <stdint.h>
#include <math.h>

// ---------------- problem constants ----------------
#define M_TOTAL 32768
#define KD      1024
#define N_TOTAL 4112
#define SEC_W   1024
#define Q_ELEMS 33554432ULL          // 32768*1024
#define NPAD    4352                 // 17 * 256

// ---------------- GEMM config ----------------
#define BM 128
#define BN 256
#define BK 32                         // k elements per tile (bf16: 64B rows)
#define STAGES 3
#define NTHREADS 512                  // 16 warps: 2 (M) x 8 (N), warp tile 64x32
#define ROWB 80                       // bytes per smem row (64 data + 16 pad)
#define A_PLANE (BM * ROWB)           // 10240 B
#define B_PLANE (BN * ROWB)           // 20480 B
#define STAGE_BYTES (2 * A_PLANE + 2 * B_PLANE)    // 61440
#define SMEM_BYTES (STAGES * STAGE_BYTES)          // 184320

// ---------------- scratch: bf16 hi/lo planes (16B-aligned) ----------------
__device__ uint4 g_Xhi[(size_t)M_TOTAL * KD / 8];   // 64 MB
__device__ uint4 g_Xlo[(size_t)M_TOTAL * KD / 8];   // 64 MB
__device__ uint4 g_Whi[(size_t)NPAD * KD / 8];      // 8.9 MB
__device__ uint4 g_Wlo[(size_t)NPAD * KD / 8];      // 8.9 MB

// ---------------- helpers ----------------
__device__ __forceinline__ uint32_t smem_u32(const void* p) {
    uint32_t a;
    asm("{ .reg .u64 t; cvta.to.shared.u64 t, %1; cvt.u32.u64 %0, t; }" : "=r"(a) : "l"(p));
    return a;
}
__device__ __forceinline__ void cp16(uint32_t dst, const void* src) {
    asm volatile("cp.async.cg.shared.global [%0], [%1], 16;" :: "r"(dst), "l"(src) : "memory");
}
#define CP_COMMIT() asm volatile("cp.async.commit_group;" ::: "memory")
#define CP_WAIT1()  asm volatile("cp.async.wait_group 1;" ::: "memory")

__device__ __forceinline__ void ldsm_x4(uint32_t* r, uint32_t addr) {
    asm volatile("ldmatrix.sync.aligned.m8n8.x4.shared.b16 {%0,%1,%2,%3}, [%4];"
        : "=r"(r[0]), "=r"(r[1]), "=r"(r[2]), "=r"(r[3]) : "r"(addr));
}
__device__ __forceinline__ void ldsm_x2(uint32_t* r, uint32_t addr) {
    asm volatile("ldmatrix.sync.aligned.m8n8.x2.shared.b16 {%0,%1}, [%2];"
        : "=r"(r[0]), "=r"(r[1]) : "r"(addr));
}
__device__ __forceinline__ void mma_bf16(float* d, const uint32_t* a, const uint32_t* b) {
    asm volatile(
        "mma.sync.aligned.m16n8k16.row.col.f32.bf16.bf16.f32 "
        "{%0,%1,%2,%3}, {%4,%5,%6,%7}, {%8,%9}, {%0,%1,%2,%3};"
        : "+f"(d[0]), "+f"(d[1]), "+f"(d[2]), "+f"(d[3])
        : "r"(a[0]), "r"(a[1]), "r"(a[2]), "r"(a[3]), "r"(b[0]), "r"(b[1]));
}

// ---------------- fp32 -> bf16 hi/lo split pre-passes ----------------
__global__ __launch_bounds__(256)
void cvt_x_kernel(const float* __restrict__ X)
{
    const size_t i8 = ((size_t)blockIdx.x * 256 + threadIdx.x) * 8;
    float4 a = *(const float4*)(X + i8);
    float4 b = *(const float4*)(X + i8 + 4);
    float f[8] = {a.x, a.y, a.z, a.w, b.x, b.y, b.z, b.w};
    union { __nv_bfloat16 h[8]; uint4 u; } H, L;
    #pragma unroll
    for (int j = 0; j < 8; ++j) {
        __nv_bfloat16 h = __float2bfloat16(f[j]);
        H.h[j] = h;
        L.h[j] = __float2bfloat16(f[j] - __bfloat162float(h));
    }
    g_Xhi[i8 >> 3] = H.u;
    g_Xlo[i8 >> 3] = L.u;
}

__global__ __launch_bounds__(256)
void cvt_w_kernel(const float* __restrict__ W)
{
    const size_t i8 = ((size_t)blockIdx.x * 256 + threadIdx.x) * 8;
    const int row = (int)(i8 >> 10);
    float f[8] = {0,0,0,0,0,0,0,0};
    if (row < N_TOTAL) {
        float4 a = *(const float4*)(W + i8);
        float4 b = *(const float4*)(W + i8 + 4);
        f[0]=a.x; f[1]=a.y; f[2]=a.z; f[3]=a.w; f[4]=b.x; f[5]=b.y; f[6]=b.z; f[7]=b.w;
    }
    union { __nv_bfloat16 h[8]; uint4 u; } H, L;
    #pragma unroll
    for (int j = 0; j < 8; ++j) {
        __nv_bfloat16 h = __float2bfloat16(f[j]);
        H.h[j] = h;
        L.h[j] = __float2bfloat16(f[j] - __bfloat162float(h));
    }
    g_Whi[i8 >> 3] = H.u;
    g_Wlo[i8 >> 3] = L.u;
}

// ---------------- fused epilogue store ----------------
__device__ __forceinline__ void store_pair(float* __restrict__ out, size_t r, int gc,
                                           float v0, float v1)
{
    if (gc < 4096) {
        const int sec = gc >> 10;
        float* dst = out + (size_t)sec * Q_ELEMS + r * SEC_W + (gc & 1023);
        if (sec == 3) {                                   // SiLU gate
            v0 = v0 / (1.0f + expf(-v0));
            v1 = v1 / (1.0f + expf(-v1));
        }
        *(float2*)dst = make_float2(v0, v1);
    } else if (gc < N_TOTAL) {                            // sigmoid alpha
        float* dst = out + 4 * Q_ELEMS + r * 16 + (gc - 4096);
        *(float2*)dst = make_float2(1.0f / (1.0f + expf(-v0)),
                                    1.0f / (1.0f + expf(-v1)));
    }
}

// ---------------- main GEMM (bf16 3-term split, m16n8k16) ----------------
__global__ __launch_bounds__(NTHREADS, 1)
void gemm_tc_kernel(float* __restrict__ out)
{
    extern __shared__ char sm[];
    const uint32_t smbase = smem_u32(sm);

    const int tid = threadIdx.x;
    const int lane = tid & 31;
    const int wid = tid >> 5;
    const int wm = wid >> 3;           // 0..1  (64 rows each)
    const int wn = wid & 7;            // 0..7  (32 cols each)
    const int g  = lane >> 2;          // groupID
    const int t4 = lane & 3;           // thread-in-group
    const int m0 = blockIdx.y * BM;
    const int n0 = blockIdx.x * BN;

    // A ldmatrix.x4 per-thread byte offset within plane (+ mi*16*ROWB + ks*32)
    const uint32_t a_off = (uint32_t)((wm * 64 + (lane & 7) + ((lane >> 3) & 1) * 8) * ROWB
                                      + ((lane >> 4) & 1) * 16);
    // B ldmatrix.x2 per-thread byte offset within plane (+ ni*8*ROWB + ks*32)
    const int t16 = lane & 15;
    const uint32_t b_off = (uint32_t)((wn * 32 + (t16 & 7)) * ROWB
                                      + ((t16 >> 3) & 1) * 16);

    float acc[4][4][4];
    #pragma unroll
    for (int mi = 0; mi < 4; ++mi)
        #pragma unroll
        for (int ni = 0; ni < 4; ++ni)
            #pragma unroll
            for (int j = 0; j < 4; ++j) acc[mi][ni][j] = 0.0f;

    // stage loader: A 2*128*4 + B 2*256*4 = 3072 16B chunks, 6 per thread
    auto load_stage = [&](int st, int kt) {
        const uint32_t base = smbase + (uint32_t)(st * STAGE_BYTES);
        const __nv_bfloat16* srcs[4] = {
            (const __nv_bfloat16*)g_Xhi, (const __nv_bfloat16*)g_Xlo,
            (const __nv_bfloat16*)g_Whi, (const __nv_bfloat16*)g_Wlo };
        #pragma unroll
        for (int i = 0; i < 6; ++i) {
            const int c = tid + i * NTHREADS;
            if (c < 1024) {                     // A planes
                const int p = c >> 9, rem = c & 511;
                const int row = rem >> 2, q = rem & 3;
                cp16(base + (uint32_t)(p * A_PLANE + row * ROWB + q * 16),
                     srcs[p] + (size_t)(m0 + row) * KD + kt * BK + q * 8);
            } else {                            // B planes
                const int c2 = c - 1024;
                const int p = c2 >> 10, rem = c2 & 1023;
                const int row = rem >> 2, q = rem & 3;
                cp16(base + (uint32_t)(2 * A_PLANE + p * B_PLANE + row * ROWB + q * 16),
                     srcs[2 + p] + (size_t)(n0 + row) * KD + kt * BK + q * 8);
            }
        }
    };

    // prologue: prefetch 2 stages
    load_stage(0, 0); CP_COMMIT();
    load_stage(1, 1); CP_COMMIT();
    CP_WAIT1();
    __syncthreads();

    const int NT = KD / BK;   // 32
    #pragma unroll 1
    for (int kt = 0; kt < NT; ++kt) {
        const int st = kt % 3;
        const uint32_t stage = smbase + (uint32_t)(st * STAGE_BYTES);
        const uint32_t aHi = stage;
        const uint32_t aLo = stage + A_PLANE;
        const uint32_t bHi = stage + 2 * A_PLANE;
        const uint32_t bLo = bHi + B_PLANE;

        #pragma unroll
        for (int ks = 0; ks < 2; ++ks) {
            const uint32_t ksb = (uint32_t)(ks * 32);
            uint32_t ah[4][4], al[4][4], bh[4][2], bl[4][2];
            #pragma unroll
            for (int mi = 0; mi < 4; ++mi) {
                ldsm_x4(ah[mi], aHi + a_off + (uint32_t)(mi * 16 * ROWB) + ksb);
                ldsm_x4(al[mi], aLo + a_off + (uint32_t)(mi * 16 * ROWB) + ksb);
            }
            #pragma unroll
            for (int ni = 0; ni < 4; ++ni) {
                ldsm_x2(bh[ni], bHi + b_off + (uint32_t)(ni * 8 * ROWB) + ksb);
                ldsm_x2(bl[ni], bLo + b_off + (uint32_t)(ni * 8 * ROWB) + ksb);
            }
            #pragma unroll
            for (int mi = 0; mi < 4; ++mi)
                #pragma unroll
                for (int ni = 0; ni < 4; ++ni) {
                    mma_bf16(acc[mi][ni], ah[mi], bh[ni]);   // hi*hi
                    mma_bf16(acc[mi][ni], al[mi], bh[ni]);   // lo*hi
                    mma_bf16(acc[mi][ni], ah[mi], bl[ni]);   // hi*lo
                }
        }

        if (kt + 2 < NT) {
            load_stage((kt + 2) % 3, kt + 2);
            CP_COMMIT();
            CP_WAIT1();
        } else {
            asm volatile("cp.async.wait_all;" ::: "memory");
        }
        __syncthreads();
    }

    // ---- fused epilogue: direct fragment stores with routing/activations ----
    #pragma unroll
    for (int mi = 0; mi < 4; ++mi) {
        const size_t r0 = (size_t)(m0 + wm * 64 + mi * 16 + g);
        #pragma unroll
        for (int ni = 0; ni < 4; ++ni) {
            const int gc = n0 + wn * 32 + ni * 8 + 2 * t4;
            store_pair(out, r0,     gc, acc[mi][ni][0], acc[mi][ni][1]);
            store_pair(out, r0 + 8, gc, acc[mi][ni][2], acc[mi][ni][3]);
        }
    }
}

// ---------------- pass 2: L2-normalize full 1024-wide K rows ----------------
__global__ __launch_bounds__(256)
void knorm_kernel(float* __restrict__ kptr)
{
    const int row  = blockIdx.x * (blockDim.x >> 5) + (threadIdx.x >> 5);
    const int lane = threadIdx.x & 31;
    float* p = kptr + (size_t)row * SEC_W + lane * 32;

    float4 v[8];
    float ss = 0.0f;
    #pragma unroll
    for (int i = 0; i < 8; ++i) {
        v[i] = *(const float4*)(p + i * 4);
        ss += v[i].x * v[i].x + v[i].y * v[i].y + v[i].z * v[i].z + v[i].w * v[i].w;
    }
    #pragma unroll
    for (int off = 16; off > 0; off >>= 1)
        ss += __shfl_xor_sync(0xFFFFFFFFu, ss, off);

    const float scale = 1.0f / fmaxf(sqrtf(ss), 1e-12f);
    #pragma unroll
    for (int i = 0; i < 8; ++i) {
        v[i].x *= scale; v[i].y *= scale; v[i].z *= scale; v[i].w *= scale;
        *(float4*)(p + i * 4) = v[i];
    }
}

extern "C" void kernel_launch(void* const* d_in, const int* in_sizes, int n_in,
                              void* d_out, int out_size)
{
    const float* x = (const float*)d_in[0];   // [4, 8192, 1024] fp32
    const float* W = (const float*)d_in[1];   // [4112, 1024] fp32
    float* out = (float*)d_out;

    cudaFuncSetAttribute(gemm_tc_kernel,
                         cudaFuncAttributeMaxDynamicSharedMemorySize, SMEM_BYTES);

    // 1) fp32 -> bf16 hi/lo planes (W zero-padded to NPAD rows)
    cvt_x_kernel<<<(M_TOTAL * KD / 8) / 256, 256>>>(x);
    cvt_w_kernel<<<(NPAD * KD / 8) / 256, 256>>>(W);

    // 2) bf16 3-term split GEMM + fused routing/activation epilogue
    dim3 grid(NPAD / BN, M_TOTAL / BM);     // 17 x 256
    gemm_tc_kernel<<<grid, NTHREADS, SMEM_BYTES>>>(out);

    // 3) K row L2-normalization
    knorm_kernel<<<M_TOTAL / 8, 256>>>(out + Q_ELEMS);
}

// round 9
// speedup vs baseline: 1.2705x; 1.2705x over previous
#include <cuda_runtime.h>
#include <stdint.h>
#include <math.h>

// ---------------- problem constants ----------------
#define M_TOTAL 32768
#define KD      1024
#define N_TOTAL 4112
#define SEC_W   1024
#define Q_ELEMS 33554432ULL          // 32768*1024
#define NPAD    4352                 // 17 * 256

// ---------------- GEMM config ----------------
#define BM 128
#define BN 256
#define BK 32
#define STAGES 3
#define NTHREADS 512                  // 16 warps: 2 (M) x 8 (N), warp tile 64x32
#define SA 36                         // smem row stride in floats (32 + 4 pad)
#define A_ST_FLOATS (BM * SA)         // 4608
#define B_ST_FLOATS (BN * SA)         // 9216
#define STAGE_FLOATS (A_ST_FLOATS + B_ST_FLOATS)   // 13824
#define SMEM_BYTES (STAGES * STAGE_FLOATS * 4)     // 165888

// ---------------- scratch: tf32-rounded, zero-padded W only ----------------
__device__ float g_Wr[(size_t)NPAD * KD];      // 17.8 MB (rows >= 4112 zeroed)

// ---------------- helpers ----------------
__device__ __forceinline__ uint32_t smem_u32(const void* p) {
    uint32_t a;
    asm("{ .reg .u64 t; cvta.to.shared.u64 t, %1; cvt.u32.u64 %0, t; }" : "=r"(a) : "l"(p));
    return a;
}
__device__ __forceinline__ uint32_t f2tf32(float f) {
    uint32_t r;
    asm("cvt.rna.tf32.f32 %0, %1;" : "=r"(r) : "f"(f));
    return r;
}
__device__ __forceinline__ uint32_t u2tf32(uint32_t u) {
    uint32_t r;
    asm("cvt.rna.tf32.f32 %0, %1;" : "=r"(r) : "r"(u));
    return r;
}
__device__ __forceinline__ void cp16(uint32_t dst, const void* src) {
    asm volatile("cp.async.cg.shared.global [%0], [%1], 16;" :: "r"(dst), "l"(src) : "memory");
}
#define CP_COMMIT() asm volatile("cp.async.commit_group;" ::: "memory")
#define CP_WAIT1()  asm volatile("cp.async.wait_group 1;" ::: "memory")

__device__ __forceinline__ void ldsm_x4(uint32_t* r, uint32_t addr) {
    asm volatile("ldmatrix.sync.aligned.m8n8.x4.shared.b16 {%0,%1,%2,%3}, [%4];"
        : "=r"(r[0]), "=r"(r[1]), "=r"(r[2]), "=r"(r[3]) : "r"(addr));
}
__device__ __forceinline__ void ldsm_x2(uint32_t* r, uint32_t addr) {
    asm volatile("ldmatrix.sync.aligned.m8n8.x2.shared.b16 {%0,%1}, [%2];"
        : "=r"(r[0]), "=r"(r[1]) : "r"(addr));
}
__device__ __forceinline__ void mma_tf32(float* d, const uint32_t* a, const uint32_t* b) {
    asm volatile(
        "mma.sync.aligned.m16n8k8.row.col.f32.tf32.tf32.f32 "
        "{%0,%1,%2,%3}, {%4,%5,%6,%7}, {%8,%9}, {%0,%1,%2,%3};"
        : "+f"(d[0]), "+f"(d[1]), "+f"(d[2]), "+f"(d[3])
        : "r"(a[0]), "r"(a[1]), "r"(a[2]), "r"(a[3]), "r"(b[0]), "r"(b[1]));
}

// ---------------- W pre-pass: tf32 round + zero-pad ----------------
__global__ __launch_bounds__(256)
void cvt_w_kernel(const float* __restrict__ W)
{
    const size_t i = ((size_t)blockIdx.x * 256 + threadIdx.x) * 4;
    const int row = (int)(i >> 10);
    float4 v = make_float4(0.f, 0.f, 0.f, 0.f);
    if (row < N_TOTAL) {
        v = *(const float4*)(W + i);
        v.x = __uint_as_float(f2tf32(v.x));
        v.y = __uint_as_float(f2tf32(v.y));
        v.z = __uint_as_float(f2tf32(v.z));
        v.w = __uint_as_float(f2tf32(v.w));
    }
    *(float4*)(g_Wr + i) = v;
}

// ---------------- fused epilogue store ----------------
__device__ __forceinline__ void store_pair(float* __restrict__ out, size_t r, int gc,
                                           float v0, float v1)
{
    if (gc < 4096) {
        const int sec = gc >> 10;
        float* dst = out + (size_t)sec * Q_ELEMS + r * SEC_W + (gc & 1023);
        if (sec == 3) {                                   // SiLU gate
            v0 = v0 / (1.0f + expf(-v0));
            v1 = v1 / (1.0f + expf(-v1));
        }
        *(float2*)dst = make_float2(v0, v1);
    } else if (gc < N_TOTAL) {                            // sigmoid alpha
        float* dst = out + 4 * Q_ELEMS + r * 16 + (gc - 4096);
        *(float2*)dst = make_float2(1.0f / (1.0f + expf(-v0)),
                                    1.0f / (1.0f + expf(-v1)));
    }
}

// ---------------- main GEMM (tf32 mma.sync, in-register A rounding) ----------------
__global__ __launch_bounds__(NTHREADS, 1)
void gemm_tc_kernel(const float* __restrict__ X, float* __restrict__ out)
{
    extern __shared__ float sm[];
    const uint32_t smbase = smem_u32(sm);

    const int tid = threadIdx.x;
    const int lane = tid & 31;
    const int wid = tid >> 5;
    const int wm = wid >> 3;           // 0..1  (64 rows each)
    const int wn = wid & 7;            // 0..7  (32 cols each)
    const int g  = lane >> 2;          // groupID
    const int t4 = lane & 3;           // thread-in-group
    const int m0 = blockIdx.y * BM;
    const int n0 = blockIdx.x * BN;

    // ldmatrix per-thread source offsets (in floats, within stage)
    const int a_lrow = wm * 64 + (lane & 7) + ((lane >> 3) & 1) * 8;   // + mi*16
    const int a_lcol = ((lane >> 4) & 1) * 4;                          // + ks*8
    const int t16 = lane & 15;
    const int b_lrow = wn * 32 + (t16 & 7);                            // + ni*8
    const int b_lcol = ((t16 >> 3) & 1) * 4;                           // + ks*8

    float acc[4][4][4];
    #pragma unroll
    for (int mi = 0; mi < 4; ++mi)
        #pragma unroll
        for (int ni = 0; ni < 4; ++ni)
            #pragma unroll
            for (int j = 0; j < 4; ++j) acc[mi][ni][j] = 0.0f;

    // stage loader: 3072 16B chunks (A raw fp32 from X: 1024, B from g_Wr: 2048)
    auto load_stage = [&](int st, int kt) {
        const uint32_t base = smbase + (uint32_t)(st * STAGE_FLOATS * 4);
        #pragma unroll
        for (int i = 0; i < 6; ++i) {
            const int c = tid + i * NTHREADS;
            if (c < 1024) {
                const int row = c >> 3, q = c & 7;
                cp16(base + (uint32_t)((row * SA + q * 4) * 4),
                     X + (size_t)(m0 + row) * KD + kt * BK + q * 4);
            } else {
                const int c2 = c - 1024;
                const int row = c2 >> 3, q = c2 & 7;
                cp16(base + (uint32_t)((A_ST_FLOATS + row * SA + q * 4) * 4),
                     g_Wr + (size_t)(n0 + row) * KD + kt * BK + q * 4);
            }
        }
    };

    // prologue: prefetch 2 stages
    load_stage(0, 0); CP_COMMIT();
    load_stage(1, 1); CP_COMMIT();
    CP_WAIT1();
    __syncthreads();

    const int NT = KD / BK;   // 32
    #pragma unroll 1
    for (int kt = 0; kt < NT; ++kt) {
        const int st = kt % 3;
        const uint32_t aStage = smbase + (uint32_t)(st * STAGE_FLOATS * 4);
        const uint32_t bStage = aStage + (uint32_t)(A_ST_FLOATS * 4);

        #pragma unroll
        for (int ks = 0; ks < 4; ++ks) {
            uint32_t a[4][4], b[4][2];
            #pragma unroll
            for (int mi = 0; mi < 4; ++mi)
                ldsm_x4(a[mi], aStage +
                    (uint32_t)(((a_lrow + mi * 16) * SA + ks * 8 + a_lcol) * 4));
            #pragma unroll
            for (int ni = 0; ni < 4; ++ni)
                ldsm_x2(b[ni], bStage +
                    (uint32_t)(((b_lrow + ni * 8) * SA + ks * 8 + b_lcol) * 4));
            // round raw fp32 A fragments to tf32 (RNA) — identical numerics to pre-pass
            #pragma unroll
            for (int mi = 0; mi < 4; ++mi)
                #pragma unroll
                for (int j = 0; j < 4; ++j)
                    a[mi][j] = u2tf32(a[mi][j]);
            #pragma unroll
            for (int mi = 0; mi < 4; ++mi)
                #pragma unroll
                for (int ni = 0; ni < 4; ++ni)
                    mma_tf32(acc[mi][ni], a[mi], b[ni]);
        }

        if (kt + 2 < NT) {
            load_stage((kt + 2) % 3, kt + 2);
            CP_COMMIT();
            CP_WAIT1();
        } else {
            asm volatile("cp.async.wait_all;" ::: "memory");
        }
        __syncthreads();
    }

    // ---- fused epilogue: direct fragment stores with routing/activations ----
    #pragma unroll
    for (int mi = 0; mi < 4; ++mi) {
        const size_t r0 = (size_t)(m0 + wm * 64 + mi * 16 + g);
        #pragma unroll
        for (int ni = 0; ni < 4; ++ni) {
            const int gc = n0 + wn * 32 + ni * 8 + 2 * t4;
            store_pair(out, r0,     gc, acc[mi][ni][0], acc[mi][ni][1]);
            store_pair(out, r0 + 8, gc, acc[mi][ni][2], acc[mi][ni][3]);
        }
    }
}

// ---------------- pass 2: L2-normalize full 1024-wide K rows ----------------
__global__ __launch_bounds__(256)
void knorm_kernel(float* __restrict__ kptr)
{
    const int row  = blockIdx.x * (blockDim.x >> 5) + (threadIdx.x >> 5);
    const int lane = threadIdx.x & 31;
    float* p = kptr + (size_t)row * SEC_W + lane * 32;

    float4 v[8];
    float ss = 0.0f;
    #pragma unroll
    for (int i = 0; i < 8; ++i) {
        v[i] = *(const float4*)(p + i * 4);
        ss += v[i].x * v[i].x + v[i].y * v[i].y + v[i].z * v[i].z + v[i].w * v[i].w;
    }
    #pragma unroll
    for (int off = 16; off > 0; off >>= 1)
        ss += __shfl_xor_sync(0xFFFFFFFFu, ss, off);

    const float scale = 1.0f / fmaxf(sqrtf(ss), 1e-12f);
    #pragma unroll
    for (int i = 0; i < 8; ++i) {
        v[i].x *= scale; v[i].y *= scale; v[i].z *= scale; v[i].w *= scale;
        *(float4*)(p + i * 4) = v[i];
    }
}

extern "C" void kernel_launch(void* const* d_in, const int* in_sizes, int n_in,
                              void* d_out, int out_size)
{
    const float* x = (const float*)d_in[0];   // [4, 8192, 1024] fp32
    const float* W = (const float*)d_in[1];   // [4112, 1024] fp32
    float* out = (float*)d_out;

    cudaFuncSetAttribute(gemm_tc_kernel,
                         cudaFuncAttributeMaxDynamicSharedMemorySize, SMEM_BYTES);

    // 1) round W to tf32 + zero-pad rows to NPAD (X is rounded in-register in the GEMM)
    cvt_w_kernel<<<(NPAD * KD / 4) / 256, 256>>>(W);

    // 2) tf32 mma.sync GEMM + fused routing/activation epilogue
    dim3 grid(NPAD / BN, M_TOTAL / BM);     // 17 x 256
    gemm_tc_kernel<<<grid, NTHREADS, SMEM_BYTES>>>(x, out);

    // 3) K row L2-normalization
    knorm_kernel<<<M_TOTAL / 8, 256>>>(out + Q_ELEMS);
}